// round 15
// baseline (speedup 1.0000x reference)
#include <cuda_runtime.h>
#include <cuda_fp16.h>
#include <cstdint>
#include <cstddef>

#define N_NODES 100000
#define B_BATCH 20000
#define K_NBR   10
#define F_DIM   256
#define H_DIM   128

// ---------------------------------------------------------------------------
// Device scratch
// ---------------------------------------------------------------------------
// Unified per-node table: [h1(128) | k~(128) | h3(128)] fp16.
//   score_ij = h1_i . k~_j   (k~ = h2 @ M^T, M = W1b @ W2b^T)
//   out_b    = (sum_j colw_j h3_j) @ W3b
__device__ __half g_tab[(size_t)N_NODES * 384];
__device__ __half g_u[(size_t)B_BATCH * 128];    // attention row reductions
__device__ uint2 g_Ba[3 * 16 * 512];             // GEMM1 B fragments (W1a..W3a)
__device__ uint2 g_Bb[3 *  8 * 512];             // slot1: M^T, slot2: W3b

// ---------------------------------------------------------------------------
// Helpers
// ---------------------------------------------------------------------------
__device__ __forceinline__ uint32_t smem_u32(const void* p) {
    uint32_t a;
    asm("{ .reg .u64 t; cvta.to.shared.u64 t, %1; cvt.u32.u64 %0, t; }"
        : "=r"(a) : "l"(p));
    return a;
}
__device__ __forceinline__ uint32_t pack_f16x2(float a, float b) {
    half2 h = __floats2half2_rn(a, b);
    return *(uint32_t*)&h;
}
__device__ __forceinline__ float tanh_fast(float x) {
    float y;
    asm("tanh.approx.f32 %0, %1;" : "=f"(y) : "f"(x));
    return y;
}
__device__ __forceinline__ void ldm4(uint32_t* r, uint32_t addr) {
    asm volatile("ldmatrix.sync.aligned.m8n8.x4.shared.b16 {%0,%1,%2,%3}, [%4];"
                 : "=r"(r[0]), "=r"(r[1]), "=r"(r[2]), "=r"(r[3]) : "r"(addr));
}
__device__ __forceinline__ void mma16816(float* d, const uint32_t* a,
                                         uint32_t b0, uint32_t b1) {
    asm volatile(
        "mma.sync.aligned.m16n8k16.row.col.f32.f16.f16.f32 "
        "{%0,%1,%2,%3}, {%4,%5,%6,%7}, {%8,%9}, {%0,%1,%2,%3};"
        : "+f"(d[0]), "+f"(d[1]), "+f"(d[2]), "+f"(d[3])
        : "r"(a[0]), "r"(a[1]), "r"(a[2]), "r"(a[3]), "r"(b0), "r"(b1));
}

// ---------------------------------------------------------------------------
// Kernel 0a: prepack W1a/W2a/W3a (GEMM1) and W3b (out-GEMM) fragments.
// Grid 112 = (48 Ba + 8 Bb[p=2]) x 2 halves.
// ---------------------------------------------------------------------------
__global__ void __launch_bounds__(256) prep_weights_kernel(
    const float* __restrict__ W1a, const float* __restrict__ W2a,
    const float* __restrict__ W3a, const float* __restrict__ W3b)
{
    __shared__ float st[16][68];
    const float* Wa[3] = {W1a, W2a, W3a};

    const int bx2  = blockIdx.x >> 1;
    const int half = blockIdx.x & 1;
    const int tid  = threadIdx.x;
    const float* W;
    uint2* dstbase;
    int ks;
    if (bx2 < 48) {                               // Ba: p(3) x ks(16)
        int p = bx2 >> 4; ks = bx2 & 15;
        W = Wa[p];
        dstbase = g_Ba + (size_t)(p * 16 + ks) * 512;
    } else {                                      // Bb p=2: W3b, ks(8)
        ks = bx2 - 48;
        W = W3b;
        dstbase = g_Bb + (size_t)(2 * 8 + ks) * 512;
    }

    const float* src = W + (size_t)ks * 16 * H_DIM + half * 64;
    {
        int r  = tid >> 4;
        int c4 = tid & 15;
        float4 v = *(const float4*)(src + r * H_DIM + c4 * 4);
        st[r][c4 * 4 + 0] = v.x;
        st[r][c4 * 4 + 1] = v.y;
        st[r][c4 * 4 + 2] = v.z;
        st[r][c4 * 4 + 3] = v.w;
    }
    __syncthreads();

    {
        int e    = half * 256 + tid;
        int nt   = e >> 5;
        int lane = e & 31;
        int kl   = (lane & 3) * 2;
        int n    = nt * 8 + (lane >> 2) - half * 64;
        uint2 fr;
        fr.x = pack_f16x2(st[kl][n],     st[kl + 1][n]);
        fr.y = pack_f16x2(st[kl + 8][n], st[kl + 9][n]);
        dstbase[e] = fr;
    }
}

// ---------------------------------------------------------------------------
// Kernel 0b: M^T fragments: B[k][n] = M[n][k] = sum_c W1b[n][c] W2b[k][c].
// fp32 dots, fp16 pack, into g_Bb slot p=1. Grid 8 (one per kstep).
// ---------------------------------------------------------------------------
__global__ void __launch_bounds__(256) prep_M_kernel(
    const float* __restrict__ W1b, const float* __restrict__ W2b)
{
    const int ks  = blockIdx.x;
    const int tid = threadIdx.x;
    for (int e = tid; e < 512; e += 256) {
        int nt   = e >> 5;
        int lane = e & 31;
        int k0   = ks * 16 + (lane & 3) * 2;
        int n    = nt * 8 + (lane >> 2);
        const float* rn  = W1b + (size_t)n * H_DIM;
        const float* rk0 = W2b + (size_t)k0 * H_DIM;
        const float* rk1 = W2b + (size_t)(k0 + 1) * H_DIM;
        const float* rk8 = W2b + (size_t)(k0 + 8) * H_DIM;
        const float* rk9 = W2b + (size_t)(k0 + 9) * H_DIM;
        float s00 = 0.f, s01 = 0.f, s10 = 0.f, s11 = 0.f;
        for (int c = 0; c < H_DIM; c += 4) {
            float4 a  = *(const float4*)(rn + c);
            float4 b0 = *(const float4*)(rk0 + c);
            float4 b1 = *(const float4*)(rk1 + c);
            float4 b8 = *(const float4*)(rk8 + c);
            float4 b9 = *(const float4*)(rk9 + c);
            s00 = fmaf(a.x, b0.x, s00); s00 = fmaf(a.y, b0.y, s00);
            s00 = fmaf(a.z, b0.z, s00); s00 = fmaf(a.w, b0.w, s00);
            s01 = fmaf(a.x, b1.x, s01); s01 = fmaf(a.y, b1.y, s01);
            s01 = fmaf(a.z, b1.z, s01); s01 = fmaf(a.w, b1.w, s01);
            s10 = fmaf(a.x, b8.x, s10); s10 = fmaf(a.y, b8.y, s10);
            s10 = fmaf(a.z, b8.z, s10); s10 = fmaf(a.w, b8.w, s10);
            s11 = fmaf(a.x, b9.x, s11); s11 = fmaf(a.y, b9.y, s11);
            s11 = fmaf(a.z, b9.z, s11); s11 = fmaf(a.w, b9.w, s11);
        }
        uint2 fr;
        fr.x = pack_f16x2(s00, s01);
        fr.y = pack_f16x2(s10, s11);
        g_Bb[(size_t)(1 * 8 + ks) * 512 + e] = fr;
    }
}

// ---------------------------------------------------------------------------
// Kernel 1: HMMA precompute. CTA = 64x128, 8 warps 2m x 4n.
// p=0: GEMM1 -> tanh -> store h1.  p=1: GEMM1 -> tanh -> H smem ->
// GEMM2(M^T) -> store k~.  p=2: GEMM1 -> tanh -> store h3.
// ---------------------------------------------------------------------------
#define XSTR 264
#define HSTR 136
#define X_OFF 0u
#define H_OFF 33792u                     // 64*264*2
#define PC_SMEM 51200u

__global__ void __launch_bounds__(256, 2) precompute_mma_kernel(
    const float* __restrict__ embed)
{
    extern __shared__ unsigned char smem[];
    const uint32_t sbase = smem_u32(smem);
    const int tid  = threadIdx.x;
    const int wid  = tid >> 5;
    const int lane = tid & 31;
    const int wm   = wid & 1;
    const int wn   = wid >> 1;
    const long brow = (long)blockIdx.x * 64;

    const uint32_t loffX = (uint32_t)((lane & 15) * XSTR + (lane >> 4) * 8) * 2;
    const uint32_t loffH = (uint32_t)((lane & 15) * HSTR + (lane >> 4) * 8) * 2;

    for (int i = tid; i < 64 * 64; i += 256) {
        int r  = i >> 6;
        int c4 = i & 63;
        long grow = brow + r;
        float4 v = make_float4(0.f, 0.f, 0.f, 0.f);
        if (grow < N_NODES) v = *(const float4*)(embed + grow * F_DIM + c4 * 4);
        uint32_t off = ((uint32_t)r * XSTR + c4 * 4) * 2;
        *(uint32_t*)(smem + X_OFF + off)     = pack_f16x2(v.x, v.y);
        *(uint32_t*)(smem + X_OFF + off + 4) = pack_f16x2(v.z, v.w);
    }
    __syncthreads();

    const int rbase = (lane >> 2);
    const int cbase = (lane & 3) * 2;

    for (int p = 0; p < 3; p++) {
        float acc[2][4][4];
        #pragma unroll
        for (int mt = 0; mt < 2; mt++)
            #pragma unroll
            for (int nt = 0; nt < 4; nt++)
                #pragma unroll
                for (int c = 0; c < 4; c++) acc[mt][nt][c] = 0.f;

        // ---- GEMM1: X[64,256] @ Wa_p -> 64x128 ----
        {
            const uint2* pb = g_Ba + (size_t)(p * 16) * 512 + (wn * 4) * 32 + lane;
            uint2 bf[4], bn[4];
            #pragma unroll
            for (int j = 0; j < 4; j++) bf[j] = pb[j * 32];
            for (int ks = 0; ks < 16; ks++) {
                const uint2* np = pb + (ks + 1) * 512;
                #pragma unroll
                for (int j = 0; j < 4; j++)
                    bn[j] = (ks < 15) ? np[j * 32] : make_uint2(0u, 0u);
                uint32_t a[2][4];
                uint32_t kb = (uint32_t)ks * 32;
                #pragma unroll
                for (int mt = 0; mt < 2; mt++) {
                    uint32_t ro = (uint32_t)(wm * 32 + mt * 16) * XSTR * 2;
                    ldm4(a[mt], sbase + X_OFF + ro + kb + loffX);
                }
                #pragma unroll
                for (int j = 0; j < 4; j++) {
                    #pragma unroll
                    for (int mt = 0; mt < 2; mt++)
                        mma16816(acc[mt][j], a[mt], bf[j].x, bf[j].y);
                }
                #pragma unroll
                for (int j = 0; j < 4; j++) bf[j] = bn[j];
            }
        }

        if (p != 1) {
            // ---- Direct epilogue: tanh -> g_tab (h1 at 0, h3 at 256) ----
            const int toff = (p == 0) ? 0 : 256;
            #pragma unroll
            for (int mt = 0; mt < 2; mt++) {
                #pragma unroll
                for (int nt = 0; nt < 4; nt++) {
                    int col = wn * 32 + nt * 8 + cbase;
                    long r0 = brow + wm * 32 + mt * 16 + rbase;
                    float t0 = tanh_fast(acc[mt][nt][0]);
                    float t1 = tanh_fast(acc[mt][nt][1]);
                    float t2 = tanh_fast(acc[mt][nt][2]);
                    float t3 = tanh_fast(acc[mt][nt][3]);
                    if (r0 < N_NODES)
                        *(uint32_t*)(g_tab + r0 * 384 + toff + col) =
                            pack_f16x2(t0, t1);
                    if (r0 + 8 < N_NODES)
                        *(uint32_t*)(g_tab + (r0 + 8) * 384 + toff + col) =
                            pack_f16x2(t2, t3);
                }
            }
            continue;
        }

        // ---- p == 1: tanh -> H smem, then GEMM2 with M^T -> k~ ----
        #pragma unroll
        for (int mt = 0; mt < 2; mt++) {
            #pragma unroll
            for (int nt = 0; nt < 4; nt++) {
                int col = wn * 32 + nt * 8 + cbase;
                int r0  = wm * 32 + mt * 16 + rbase;
                float t0 = tanh_fast(acc[mt][nt][0]);
                float t1 = tanh_fast(acc[mt][nt][1]);
                float t2 = tanh_fast(acc[mt][nt][2]);
                float t3 = tanh_fast(acc[mt][nt][3]);
                uint32_t o0 = ((uint32_t)r0 * HSTR + col) * 2;
                uint32_t o1 = ((uint32_t)(r0 + 8) * HSTR + col) * 2;
                *(uint32_t*)(smem + H_OFF + o0) = pack_f16x2(t0, t1);
                *(uint32_t*)(smem + H_OFF + o1) = pack_f16x2(t2, t3);
            }
        }
        __syncthreads();

        #pragma unroll
        for (int mt = 0; mt < 2; mt++)
            #pragma unroll
            for (int nt = 0; nt < 4; nt++)
                #pragma unroll
                for (int c = 0; c < 4; c++) acc[mt][nt][c] = 0.f;

        {
            const uint2* pb = g_Bb + (size_t)(1 * 8) * 512 + (wn * 4) * 32 + lane;
            uint2 bf[4], bn[4];
            #pragma unroll
            for (int j = 0; j < 4; j++) bf[j] = pb[j * 32];
            for (int ks = 0; ks < 8; ks++) {
                const uint2* np = pb + (ks + 1) * 512;
                #pragma unroll
                for (int j = 0; j < 4; j++)
                    bn[j] = (ks < 7) ? np[j * 32] : make_uint2(0u, 0u);
                uint32_t a[2][4];
                uint32_t kb = (uint32_t)ks * 32;
                #pragma unroll
                for (int mt = 0; mt < 2; mt++) {
                    uint32_t ro = (uint32_t)(wm * 32 + mt * 16) * HSTR * 2;
                    ldm4(a[mt], sbase + H_OFF + ro + kb + loffH);
                }
                #pragma unroll
                for (int j = 0; j < 4; j++) {
                    #pragma unroll
                    for (int mt = 0; mt < 2; mt++)
                        mma16816(acc[mt][j], a[mt], bf[j].x, bf[j].y);
                }
                #pragma unroll
                for (int j = 0; j < 4; j++) bf[j] = bn[j];
            }
        }

        #pragma unroll
        for (int mt = 0; mt < 2; mt++) {
            #pragma unroll
            for (int nt = 0; nt < 4; nt++) {
                int col = wn * 32 + nt * 8 + cbase;
                long r0 = brow + wm * 32 + mt * 16 + rbase;
                if (r0 < N_NODES)
                    *(uint32_t*)(g_tab + r0 * 384 + 128 + col) =
                        pack_f16x2(acc[mt][nt][0], acc[mt][nt][1]);
                if (r0 + 8 < N_NODES)
                    *(uint32_t*)(g_tab + (r0 + 8) * 384 + 128 + col) =
                        pack_f16x2(acc[mt][nt][2], acc[mt][nt][3]);
            }
        }
        // H smem is not rewritten afterwards; no trailing barrier needed.
    }
}

// ---------------------------------------------------------------------------
// Kernel 2: warp-autonomous attention; writes u_b = sum_j colw_j h3_j (fp16).
// ---------------------------------------------------------------------------
__global__ void __launch_bounds__(256) attention_kernel(
    const int* __restrict__ neighbors)
{
    const int b    = blockIdx.x * 8 + (threadIdx.x >> 5);
    const int lane = threadIdx.x & 31;

    int mynode = 0;
    if (lane < K_NBR) mynode = neighbors[(size_t)b * K_NBR + lane];

    int node[K_NBR];
    #pragma unroll
    for (int j = 0; j < K_NBR; j++)
        node[j] = __shfl_sync(0xffffffffu, mynode, j);

    const int d = lane * 4;

    float4 qv[K_NBR], kv[K_NBR];
    #pragma unroll
    for (int j = 0; j < K_NBR; j++) {
        const __half* base = g_tab + (size_t)node[j] * 384;
        uint2 qr = *(const uint2*)(base + d);
        uint2 kr = *(const uint2*)(base + 128 + d);
        float2 q0 = __half22float2(*(half2*)&qr.x);
        float2 q1 = __half22float2(*(half2*)&qr.y);
        float2 k0 = __half22float2(*(half2*)&kr.x);
        float2 k1 = __half22float2(*(half2*)&kr.y);
        qv[j] = make_float4(q0.x, q0.y, q1.x, q1.y);
        kv[j] = make_float4(k0.x, k0.y, k1.x, k1.y);
    }

    float scol[K_NBR];
    #pragma unroll
    for (int i = 0; i < K_NBR; i++) {
        #pragma unroll
        for (int j = 0; j < K_NBR; j++) {
            float s = qv[i].x * kv[j].x;
            s = fmaf(qv[i].y, kv[j].y, s);
            s = fmaf(qv[i].z, kv[j].z, s);
            s = fmaf(qv[i].w, kv[j].w, s);
            s += __shfl_xor_sync(0xffffffffu, s, 16);
            s += __shfl_xor_sync(0xffffffffu, s, 8);
            s += __shfl_xor_sync(0xffffffffu, s, 4);
            s += __shfl_xor_sync(0xffffffffu, s, 2);
            s += __shfl_xor_sync(0xffffffffu, s, 1);
            if (lane == j) scol[i] = s;
        }
    }

    float4 vv[K_NBR];
    #pragma unroll
    for (int j = 0; j < K_NBR; j++) {
        uint2 vr = *(const uint2*)(g_tab + (size_t)node[j] * 384 + 256 + d);
        float2 v0 = __half22float2(*(half2*)&vr.x);
        float2 v1 = __half22float2(*(half2*)&vr.y);
        vv[j] = make_float4(v0.x, v0.y, v1.x, v1.y);
    }

    float colw = 0.f;
    #pragma unroll
    for (int i = 0; i < K_NBR; i++) {
        float s = (lane < K_NBR) ? scol[i] : -1e30f;
        float m = s;
        m = fmaxf(m, __shfl_xor_sync(0xffffffffu, m, 16));
        m = fmaxf(m, __shfl_xor_sync(0xffffffffu, m, 8));
        m = fmaxf(m, __shfl_xor_sync(0xffffffffu, m, 4));
        m = fmaxf(m, __shfl_xor_sync(0xffffffffu, m, 2));
        m = fmaxf(m, __shfl_xor_sync(0xffffffffu, m, 1));
        float e = (lane < K_NBR) ? __expf(s - m) : 0.f;
        float sum = e;
        sum += __shfl_xor_sync(0xffffffffu, sum, 16);
        sum += __shfl_xor_sync(0xffffffffu, sum, 8);
        sum += __shfl_xor_sync(0xffffffffu, sum, 4);
        sum += __shfl_xor_sync(0xffffffffu, sum, 2);
        sum += __shfl_xor_sync(0xffffffffu, sum, 1);
        colw += e / sum;
    }

    float4 o = make_float4(0.f, 0.f, 0.f, 0.f);
    #pragma unroll
    for (int j = 0; j < K_NBR; j++) {
        float cw = __shfl_sync(0xffffffffu, colw, j);
        o.x = fmaf(cw, vv[j].x, o.x);
        o.y = fmaf(cw, vv[j].y, o.y);
        o.z = fmaf(cw, vv[j].z, o.z);
        o.w = fmaf(cw, vv[j].w, o.w);
    }
    uint2 uo;
    uo.x = pack_f16x2(o.x, o.y);
    uo.y = pack_f16x2(o.z, o.w);
    *(uint2*)(g_u + (size_t)b * 128 + d) = uo;
}

// ---------------------------------------------------------------------------
// Kernel 3: out = U[20000,128] @ W3b -> d_out (fp32).
// ---------------------------------------------------------------------------
__global__ void __launch_bounds__(256, 2) out_gemm_kernel(float* __restrict__ out)
{
    __shared__ __align__(16) unsigned char smem[64 * HSTR * 2];  // 17408 B
    const uint32_t sbase = smem_u32(smem);
    const int tid  = threadIdx.x;
    const int wid  = tid >> 5;
    const int lane = tid & 31;
    const int wm   = wid & 1;
    const int wn   = wid >> 1;
    const long brow = (long)blockIdx.x * 64;

    const uint32_t loffH = (uint32_t)((lane & 15) * HSTR + (lane >> 4) * 8) * 2;

    // Load U tile [64][128] fp16 -> smem (HSTR layout).
    // 64 uint32 (=128 halves) per row.  [FIXED: was 64*32 / c4&31]
    for (int i = tid; i < 64 * 64; i += 256) {
        int r  = i >> 6;
        int c4 = i & 63;                 // uint32 index within row
        long gr = brow + r;
        uint32_t v = 0u;
        if (gr < B_BATCH)
            v = *(const uint32_t*)(g_u + gr * 128 + c4 * 2);
        *(uint32_t*)(smem + ((uint32_t)r * HSTR + c4 * 2) * 2) = v;
    }
    __syncthreads();

    const int rbase = (lane >> 2);
    const int cbase = (lane & 3) * 2;

    float acc[2][4][4];
    #pragma unroll
    for (int mt = 0; mt < 2; mt++)
        #pragma unroll
        for (int nt = 0; nt < 4; nt++)
            #pragma unroll
            for (int c = 0; c < 4; c++) acc[mt][nt][c] = 0.f;

    const uint2* pb = g_Bb + (size_t)(2 * 8) * 512 + (wn * 4) * 32 + lane;
    uint2 bf[4], bn[4];
    #pragma unroll
    for (int j = 0; j < 4; j++) bf[j] = pb[j * 32];
    for (int ks = 0; ks < 8; ks++) {
        const uint2* np = pb + (ks + 1) * 512;
        #pragma unroll
        for (int j = 0; j < 4; j++)
            bn[j] = (ks < 7) ? np[j * 32] : make_uint2(0u, 0u);
        uint32_t a[2][4];
        uint32_t kb = (uint32_t)ks * 32;
        #pragma unroll
        for (int mt = 0; mt < 2; mt++) {
            uint32_t ro = (uint32_t)(wm * 32 + mt * 16) * HSTR * 2;
            ldm4(a[mt], sbase + ro + kb + loffH);
        }
        #pragma unroll
        for (int j = 0; j < 4; j++) {
            #pragma unroll
            for (int mt = 0; mt < 2; mt++)
                mma16816(acc[mt][j], a[mt], bf[j].x, bf[j].y);
        }
        #pragma unroll
        for (int j = 0; j < 4; j++) bf[j] = bn[j];
    }

    #pragma unroll
    for (int mt = 0; mt < 2; mt++) {
        #pragma unroll
        for (int nt = 0; nt < 4; nt++) {
            int col = wn * 32 + nt * 8 + cbase;
            long r0 = brow + wm * 32 + mt * 16 + rbase;
            if (r0 < B_BATCH)
                *(float2*)(out + r0 * H_DIM + col) =
                    make_float2(acc[mt][nt][0], acc[mt][nt][1]);
            if (r0 + 8 < B_BATCH)
                *(float2*)(out + (r0 + 8) * H_DIM + col) =
                    make_float2(acc[mt][nt][2], acc[mt][nt][3]);
        }
    }
}

// ---------------------------------------------------------------------------
extern "C" void kernel_launch(void* const* d_in, const int* in_sizes, int n_in,
                              void* d_out, int out_size) {
    const int*   neighbors = (const int*)d_in[0];
    const float* embed     = (const float*)d_in[1];
    const float* W1a       = (const float*)d_in[2];
    const float* W1b       = (const float*)d_in[3];
    const float* W2a       = (const float*)d_in[4];
    const float* W2b       = (const float*)d_in[5];
    const float* W3a       = (const float*)d_in[6];
    const float* W3b       = (const float*)d_in[7];
    float* out = (float*)d_out;

    prep_weights_kernel<<<112, 256>>>(W1a, W2a, W3a, W3b);
    prep_M_kernel<<<8, 256>>>(W1b, W2b);

    cudaFuncSetAttribute(precompute_mma_kernel,
                         cudaFuncAttributeMaxDynamicSharedMemorySize,
                         (int)PC_SMEM);
    const int grid1 = (N_NODES + 63) / 64;     // 1563
    precompute_mma_kernel<<<grid1, 256, PC_SMEM>>>(embed);

    attention_kernel<<<B_BATCH / 8, 256>>>(neighbors);

    const int grid3 = (B_BATCH + 63) / 64;     // 313
    out_gemm_kernel<<<grid3, 256>>>(out);
}

// round 16
// speedup vs baseline: 1.3864x; 1.3864x over previous
#include <cuda_runtime.h>
#include <cuda_fp16.h>
#include <cstdint>
#include <cstddef>

#define N_NODES 100000
#define B_BATCH 20000
#define K_NBR   10
#define F_DIM   256
#define H_DIM   128

// ---------------------------------------------------------------------------
// Device scratch
// ---------------------------------------------------------------------------
__device__ __half g_tab[(size_t)N_NODES * 384];  // [q|k|v] fp16, 76.8 MB
__device__ uint2 g_Ba[3 * 16 * 512];             // fp16 B fragments, GEMM1
__device__ uint2 g_Bb[3 *  8 * 512];             // fp16 B fragments, GEMM2

// ---------------------------------------------------------------------------
// Helpers
// ---------------------------------------------------------------------------
__device__ __forceinline__ uint32_t smem_u32(const void* p) {
    uint32_t a;
    asm("{ .reg .u64 t; cvta.to.shared.u64 t, %1; cvt.u32.u64 %0, t; }"
        : "=r"(a) : "l"(p));
    return a;
}
__device__ __forceinline__ uint32_t pack_f16x2(float a, float b) {
    half2 h = __floats2half2_rn(a, b);
    return *(uint32_t*)&h;
}
__device__ __forceinline__ float tanh_fast(float x) {
    float y;
    asm("tanh.approx.f32 %0, %1;" : "=f"(y) : "f"(x));
    return y;
}
__device__ __forceinline__ void ldm4(uint32_t* r, uint32_t addr) {
    asm volatile("ldmatrix.sync.aligned.m8n8.x4.shared.b16 {%0,%1,%2,%3}, [%4];"
                 : "=r"(r[0]), "=r"(r[1]), "=r"(r[2]), "=r"(r[3]) : "r"(addr));
}
__device__ __forceinline__ void mma16816(float* d, const uint32_t* a,
                                         uint32_t b0, uint32_t b1) {
    asm volatile(
        "mma.sync.aligned.m16n8k16.row.col.f32.f16.f16.f32 "
        "{%0,%1,%2,%3}, {%4,%5,%6,%7}, {%8,%9}, {%0,%1,%2,%3};"
        : "+f"(d[0]), "+f"(d[1]), "+f"(d[2]), "+f"(d[3])
        : "r"(a[0]), "r"(a[1]), "r"(a[2]), "r"(a[3]), "r"(b0), "r"(b1));
}

// ---------------------------------------------------------------------------
// Kernel 0: prepack weights into mma B-fragment layout (fp16, single term).
// ---------------------------------------------------------------------------
__global__ void __launch_bounds__(256) prep_weights_kernel(
    const float* __restrict__ W1a, const float* __restrict__ W1b,
    const float* __restrict__ W2a, const float* __restrict__ W2b,
    const float* __restrict__ W3a, const float* __restrict__ W3b)
{
    __shared__ float st[16][68];
    const float* Wa[3] = {W1a, W2a, W3a};
    const float* Wb[3] = {W1b, W2b, W3b};

    const int bx2  = blockIdx.x >> 1;
    const int half = blockIdx.x & 1;
    const int tid  = threadIdx.x;
    const float* W;
    uint2* dstbase;
    int ks;
    if (bx2 < 48) {                               // Ba: p(3) x ks(16)
        int p = bx2 >> 4; ks = bx2 & 15;
        W = Wa[p];
        dstbase = g_Ba + (size_t)(p * 16 + ks) * 512;
    } else {                                      // Bb: p(3) x ks(8)
        int i = bx2 - 48;
        int p = i >> 3; ks = i & 7;
        W = Wb[p];
        dstbase = g_Bb + (size_t)(p * 8 + ks) * 512;
    }

    const float* src = W + (size_t)ks * 16 * H_DIM + half * 64;
    {
        int r  = tid >> 4;
        int c4 = tid & 15;
        float4 v = *(const float4*)(src + r * H_DIM + c4 * 4);
        st[r][c4 * 4 + 0] = v.x;
        st[r][c4 * 4 + 1] = v.y;
        st[r][c4 * 4 + 2] = v.z;
        st[r][c4 * 4 + 3] = v.w;
    }
    __syncthreads();

    {
        int e    = half * 256 + tid;
        int nt   = e >> 5;
        int lane = e & 31;
        int kl   = (lane & 3) * 2;
        int n    = nt * 8 + (lane >> 2) - half * 64;
        uint2 fr;
        fr.x = pack_f16x2(st[kl][n],     st[kl + 1][n]);
        fr.y = pack_f16x2(st[kl + 8][n], st[kl + 9][n]);
        dstbase[e] = fr;
    }
}

// ---------------------------------------------------------------------------
// Kernel 1: HMMA precompute (R11 config: CTA 64x128, 8 warps 2m x 4n,
// warp tile 32x32, B prefetched 1 kstep ahead, unified fp16 table output).
// ---------------------------------------------------------------------------
#define XSTR 264
#define HSTR 136
#define X_OFF 0u
#define H_OFF 33792u                     // 64*264*2
#define PC_SMEM 51200u

__global__ void __launch_bounds__(256, 3) precompute_mma_kernel(
    const float* __restrict__ embed)
{
    extern __shared__ unsigned char smem[];
    const uint32_t sbase = smem_u32(smem);
    const int tid  = threadIdx.x;
    const int wid  = tid >> 5;
    const int lane = tid & 31;
    const int wm   = wid & 1;
    const int wn   = wid >> 1;
    const long brow = (long)blockIdx.x * 64;

    const uint32_t loffX = (uint32_t)((lane & 15) * XSTR + (lane >> 4) * 8) * 2;
    const uint32_t loffH = (uint32_t)((lane & 15) * HSTR + (lane >> 4) * 8) * 2;

    for (int i = tid; i < 64 * 64; i += 256) {
        int r  = i >> 6;
        int c4 = i & 63;
        long grow = brow + r;
        float4 v = make_float4(0.f, 0.f, 0.f, 0.f);
        if (grow < N_NODES) v = *(const float4*)(embed + grow * F_DIM + c4 * 4);
        uint32_t off = ((uint32_t)r * XSTR + c4 * 4) * 2;
        *(uint32_t*)(smem + X_OFF + off)     = pack_f16x2(v.x, v.y);
        *(uint32_t*)(smem + X_OFF + off + 4) = pack_f16x2(v.z, v.w);
    }
    __syncthreads();

    const int rbase = (lane >> 2);
    const int cbase = (lane & 3) * 2;

    for (int p = 0; p < 3; p++) {
        float acc[2][4][4];
        #pragma unroll
        for (int mt = 0; mt < 2; mt++)
            #pragma unroll
            for (int nt = 0; nt < 4; nt++)
                #pragma unroll
                for (int c = 0; c < 4; c++) acc[mt][nt][c] = 0.f;

        // ================= GEMM1: X[64,256] @ Wa -> 64x128 =================
        {
            const uint2* pb = g_Ba + (size_t)(p * 16) * 512 + (wn * 4) * 32 + lane;
            uint2 bf[4], bn[4];
            #pragma unroll
            for (int j = 0; j < 4; j++) bf[j] = pb[j * 32];
            for (int ks = 0; ks < 16; ks++) {
                const uint2* np = pb + (ks + 1) * 512;
                #pragma unroll
                for (int j = 0; j < 4; j++)
                    bn[j] = (ks < 15) ? np[j * 32] : make_uint2(0u, 0u);
                uint32_t a[2][4];
                uint32_t kb = (uint32_t)ks * 32;
                #pragma unroll
                for (int mt = 0; mt < 2; mt++) {
                    uint32_t ro = (uint32_t)(wm * 32 + mt * 16) * XSTR * 2;
                    ldm4(a[mt], sbase + X_OFF + ro + kb + loffX);
                }
                #pragma unroll
                for (int j = 0; j < 4; j++) {
                    #pragma unroll
                    for (int mt = 0; mt < 2; mt++)
                        mma16816(acc[mt][j], a[mt], bf[j].x, bf[j].y);
                }
                #pragma unroll
                for (int j = 0; j < 4; j++) bf[j] = bn[j];
            }
        }

        // ---- Epilogue 1: tanh.approx -> H smem (fp16) ----
        #pragma unroll
        for (int mt = 0; mt < 2; mt++) {
            #pragma unroll
            for (int nt = 0; nt < 4; nt++) {
                int col = wn * 32 + nt * 8 + cbase;
                int r0  = wm * 32 + mt * 16 + rbase;
                float t0 = tanh_fast(acc[mt][nt][0]);
                float t1 = tanh_fast(acc[mt][nt][1]);
                float t2 = tanh_fast(acc[mt][nt][2]);
                float t3 = tanh_fast(acc[mt][nt][3]);
                uint32_t o0 = ((uint32_t)r0 * HSTR + col) * 2;
                uint32_t o1 = ((uint32_t)(r0 + 8) * HSTR + col) * 2;
                *(uint32_t*)(smem + H_OFF + o0) = pack_f16x2(t0, t1);
                *(uint32_t*)(smem + H_OFF + o1) = pack_f16x2(t2, t3);
            }
        }
        __syncthreads();

        // ================= GEMM2: H[64,128] @ Wb -> 64x128 =================
        #pragma unroll
        for (int mt = 0; mt < 2; mt++)
            #pragma unroll
            for (int nt = 0; nt < 4; nt++)
                #pragma unroll
                for (int c = 0; c < 4; c++) acc[mt][nt][c] = 0.f;

        {
            const uint2* pb = g_Bb + (size_t)(p * 8) * 512 + (wn * 4) * 32 + lane;
            uint2 bf[4], bn[4];
            #pragma unroll
            for (int j = 0; j < 4; j++) bf[j] = pb[j * 32];
            for (int ks = 0; ks < 8; ks++) {
                const uint2* np = pb + (ks + 1) * 512;
                #pragma unroll
                for (int j = 0; j < 4; j++)
                    bn[j] = (ks < 7) ? np[j * 32] : make_uint2(0u, 0u);
                uint32_t a[2][4];
                uint32_t kb = (uint32_t)ks * 32;
                #pragma unroll
                for (int mt = 0; mt < 2; mt++) {
                    uint32_t ro = (uint32_t)(wm * 32 + mt * 16) * HSTR * 2;
                    ldm4(a[mt], sbase + H_OFF + ro + kb + loffH);
                }
                #pragma unroll
                for (int j = 0; j < 4; j++) {
                    #pragma unroll
                    for (int mt = 0; mt < 2; mt++)
                        mma16816(acc[mt][j], a[mt], bf[j].x, bf[j].y);
                }
                #pragma unroll
                for (int j = 0; j < 4; j++) bf[j] = bn[j];
            }
        }

        // ---- Epilogue 2: write q/k/v fp16 into unified table ----
        #pragma unroll
        for (int mt = 0; mt < 2; mt++) {
            #pragma unroll
            for (int nt = 0; nt < 4; nt++) {
                int col = wn * 32 + nt * 8 + cbase;
                long r0 = brow + wm * 32 + mt * 16 + rbase;
                if (r0 < N_NODES)
                    *(uint32_t*)(g_tab + r0 * 384 + p * 128 + col) =
                        pack_f16x2(acc[mt][nt][0], acc[mt][nt][1]);
                if (r0 + 8 < N_NODES)
                    *(uint32_t*)(g_tab + (r0 + 8) * 384 + p * 128 + col) =
                        pack_f16x2(acc[mt][nt][2], acc[mt][nt][3]);
            }
        }
        __syncthreads();
    }
}

// ---------------------------------------------------------------------------
// Kernel 2: warp-autonomous attention, low-register fp16 variant.
// k,v held as fp16 uint2 (4 halves/lane); q streamed one row ahead.
// Score partials via HFMA2, reduced in fp32 by shfl butterflies.
// ---------------------------------------------------------------------------
__global__ void __launch_bounds__(128, 6) attention_kernel(
    const int* __restrict__ neighbors, float* __restrict__ out)
{
    const int b    = blockIdx.x * 4 + (threadIdx.x >> 5);
    const int lane = threadIdx.x & 31;

    int mynode = 0;
    if (lane < K_NBR) mynode = neighbors[(size_t)b * K_NBR + lane];

    int node[K_NBR];
    #pragma unroll
    for (int j = 0; j < K_NBR; j++)
        node[j] = __shfl_sync(0xffffffffu, mynode, j);

    const int d = lane * 4;                        // dims 4l..4l+3

    // Cache all k rows (fp16: 2 regs per row)
    uint2 kv[K_NBR];
    #pragma unroll
    for (int j = 0; j < K_NBR; j++)
        kv[j] = *(const uint2*)(g_tab + (size_t)node[j] * 384 + 128 + d);

    // Score matrix: lane j retains s[i][j]; q rows streamed one ahead
    float scol[K_NBR];
    uint2 q = *(const uint2*)(g_tab + (size_t)node[0] * 384 + d);
    #pragma unroll
    for (int i = 0; i < K_NBR; i++) {
        uint2 qn = make_uint2(0u, 0u);
        if (i < K_NBR - 1)
            qn = *(const uint2*)(g_tab + (size_t)node[i + 1] * 384 + d);
        half2 q0 = *(half2*)&q.x;
        half2 q1 = *(half2*)&q.y;
        #pragma unroll
        for (int j = 0; j < K_NBR; j++) {
            half2 a = __hmul2(q0, *(half2*)&kv[j].x);
            a = __hfma2(q1, *(half2*)&kv[j].y, a);
            float s = __low2float(a) + __high2float(a);
            s += __shfl_xor_sync(0xffffffffu, s, 16);
            s += __shfl_xor_sync(0xffffffffu, s, 8);
            s += __shfl_xor_sync(0xffffffffu, s, 4);
            s += __shfl_xor_sync(0xffffffffu, s, 2);
            s += __shfl_xor_sync(0xffffffffu, s, 1);
            if (lane == j) scol[i] = s;
        }
        q = qn;
    }

    // Prefetch v rows (fp16)
    uint2 vv[K_NBR];
    #pragma unroll
    for (int j = 0; j < K_NBR; j++)
        vv[j] = *(const uint2*)(g_tab + (size_t)node[j] * 384 + 256 + d);

    // Softmax + column weights: colw[j] = sum_i exp(s_ij - m_i) / rowsum_i
    float colw = 0.f;
    #pragma unroll
    for (int i = 0; i < K_NBR; i++) {
        float s = (lane < K_NBR) ? scol[i] : -1e30f;
        float m = s;
        m = fmaxf(m, __shfl_xor_sync(0xffffffffu, m, 16));
        m = fmaxf(m, __shfl_xor_sync(0xffffffffu, m, 8));
        m = fmaxf(m, __shfl_xor_sync(0xffffffffu, m, 4));
        m = fmaxf(m, __shfl_xor_sync(0xffffffffu, m, 2));
        m = fmaxf(m, __shfl_xor_sync(0xffffffffu, m, 1));
        float e = (lane < K_NBR) ? __expf(s - m) : 0.f;
        float sum = e;
        sum += __shfl_xor_sync(0xffffffffu, sum, 16);
        sum += __shfl_xor_sync(0xffffffffu, sum, 8);
        sum += __shfl_xor_sync(0xffffffffu, sum, 4);
        sum += __shfl_xor_sync(0xffffffffu, sum, 2);
        sum += __shfl_xor_sync(0xffffffffu, sum, 1);
        colw += e / sum;
    }

    // out[b, 4l..4l+3] = sum_j colw_j * v_j
    float4 o = make_float4(0.f, 0.f, 0.f, 0.f);
    #pragma unroll
    for (int j = 0; j < K_NBR; j++) {
        float cw = __shfl_sync(0xffffffffu, colw, j);
        float2 v0 = __half22float2(*(half2*)&vv[j].x);
        float2 v1 = __half22float2(*(half2*)&vv[j].y);
        o.x = fmaf(cw, v0.x, o.x);
        o.y = fmaf(cw, v0.y, o.y);
        o.z = fmaf(cw, v1.x, o.z);
        o.w = fmaf(cw, v1.y, o.w);
    }
    *(float4*)(out + (size_t)b * H_DIM + d) = o;
}

// ---------------------------------------------------------------------------
extern "C" void kernel_launch(void* const* d_in, const int* in_sizes, int n_in,
                              void* d_out, int out_size) {
    const int*   neighbors = (const int*)d_in[0];
    const float* embed     = (const float*)d_in[1];
    const float* W1a       = (const float*)d_in[2];
    const float* W1b       = (const float*)d_in[3];
    const float* W2a       = (const float*)d_in[4];
    const float* W2b       = (const float*)d_in[5];
    const float* W3a       = (const float*)d_in[6];
    const float* W3b       = (const float*)d_in[7];
    float* out = (float*)d_out;

    prep_weights_kernel<<<144, 256>>>(W1a, W1b, W2a, W2b, W3a, W3b);

    cudaFuncSetAttribute(precompute_mma_kernel,
                         cudaFuncAttributeMaxDynamicSharedMemorySize,
                         (int)PC_SMEM);
    const int grid1 = (N_NODES + 63) / 64;     // 1563
    precompute_mma_kernel<<<grid1, 256, PC_SMEM>>>(embed);

    attention_kernel<<<B_BATCH / 4, 128>>>(neighbors, out);
}